// round 11
// baseline (speedup 1.0000x reference)
#include <cuda_runtime.h>
#include <cuda_fp16.h>

#define FD 128
#define NMAX 51200     // bins / node headroom over N=50000
#define EMAX 1700000   // edge headroom over E=1.6M

// Scratch: Wh = (W + W^T) fp16, G = feats @ Ws (fp16), feats copy (fp16).
__device__ __half g_Wh[FD * FD];
__device__ __half g_Gh[(size_t)NMAX * FD];
__device__ __half g_Fh[(size_t)NMAX * FD];
// Sort scratch: histogram/cursor and packed sorted edges {i, j, m, pad}.
__device__ int  g_hist[NMAX];
__device__ int  g_cur[NMAX];
__device__ int4 g_edges[EMAX];

// ---------------------------------------------------------------------------
// Kernel 1: Wh = fp16(W + W^T); zero output; zero histogram.
// ---------------------------------------------------------------------------
__global__ void prep_kernel(const float* __restrict__ W,
                            float* __restrict__ out, int M) {
    int t = blockIdx.x * blockDim.x + threadIdx.x;
    if (t < FD * FD) {
        int r = t >> 7;
        int c = t & 127;
        g_Wh[t] = __float2half_rn(W[t] + W[c * FD + r]);
    }
    if (t < M) out[t] = 0.0f;
    if (t < NMAX) g_hist[t] = 0;
}

// ---------------------------------------------------------------------------
// Kernel 1b: histogram of source indices.
// ---------------------------------------------------------------------------
__global__ void hist_kernel(const int* __restrict__ nbr, int E) {
    int e = blockIdx.x * blockDim.x + threadIdx.x;
    if (e < E) atomicAdd(&g_hist[nbr[e]], 1);
}

// ---------------------------------------------------------------------------
// Kernel 1c: exclusive prefix sum over N bins (single block, 1024 threads).
// ---------------------------------------------------------------------------
__global__ __launch_bounds__(1024) void scan_kernel(int N) {
    __shared__ int s[1024];
    const int tid = threadIdx.x;
    const int chunk = (N + 1023) / 1024;
    int lo = tid * chunk;
    int hi = lo + chunk;
    if (hi > N) hi = N;

    int sum = 0;
    for (int e = lo; e < hi; e++) sum += g_hist[e];
    s[tid] = sum;
    __syncthreads();
    // Hillis-Steele inclusive scan.
    for (int off = 1; off < 1024; off <<= 1) {
        int v = (tid >= off) ? s[tid - off] : 0;
        __syncthreads();
        s[tid] += v;
        __syncthreads();
    }
    int run = s[tid] - sum;   // exclusive offset for this chunk
    for (int e = lo; e < hi; e++) {
        g_cur[e] = run;
        run += g_hist[e];
    }
}

// ---------------------------------------------------------------------------
// Kernel 1d: scatter edges into i-sorted order (packed int4 per edge).
// ---------------------------------------------------------------------------
__global__ void scatter_kernel(const int* __restrict__ nbr,
                               const int* __restrict__ mol, int E) {
    int e = blockIdx.x * blockDim.x + threadIdx.x;
    if (e >= E) return;
    int i = nbr[e];
    int pos = atomicAdd(&g_cur[i], 1);
    g_edges[pos] = make_int4(i, nbr[(size_t)E + e], mol[e], 0);
}

// ---------------------------------------------------------------------------
// XOR swizzle on 16-byte chunks.
// ---------------------------------------------------------------------------
__device__ __forceinline__ int swz_off(int row, int col_halves) {
    int chunk = col_halves >> 3;
    int within = col_halves & 7;
    return row * FD + ((chunk ^ (row & 7)) << 3) + within;
}

// ---------------------------------------------------------------------------
// Kernel 2: G = feats @ Ws via HMMA (unchanged, measured-good since R6).
// ---------------------------------------------------------------------------
__global__ __launch_bounds__(256) void gemm_mma_kernel(const float* __restrict__ feats,
                                                       int N) {
    __shared__ __half sA[64 * FD];
    __shared__ __half sB[128 * FD];

    const int base = blockIdx.x * 64;
    const int tid = threadIdx.x;

    int nval = N - base;
    if (nval > 64) nval = 64;

    {
        const uint2* src = (const uint2*)g_Wh;
        for (int i = tid; i < 128 * 32; i += 256) {
            int row = i >> 5, c4 = i & 31;
            *(uint2*)&sB[swz_off(row, c4 * 4)] = src[i];
        }
    }
    {
        const float4* src = (const float4*)feats + (size_t)base * 32;
        uint2* fh_dst = (uint2*)(g_Fh + (size_t)base * FD);
        for (int i = tid; i < 64 * 32; i += 256) {
            int row = i >> 5, c4 = i & 31;
            uint2 p = make_uint2(0u, 0u);
            if (row < nval) {
                float4 v = src[i];
                __half2 h0 = __floats2half2_rn(v.x, v.y);
                __half2 h1 = __floats2half2_rn(v.z, v.w);
                p.x = *(unsigned int*)&h0;
                p.y = *(unsigned int*)&h1;
                fh_dst[i] = p;
            }
            *(uint2*)&sA[swz_off(row, c4 * 4)] = p;
        }
    }
    __syncthreads();

    const int warp = tid >> 5;
    const int lane = tid & 31;
    const int mr = warp >> 1;
    const int nc = warp & 1;

    float acc[8][4];
#pragma unroll
    for (int b = 0; b < 8; b++)
#pragma unroll
        for (int q = 0; q < 4; q++) acc[b][q] = 0.0f;

    const int arow = mr * 16 + (lane & 15);
    const int a_kchunk_base = (lane >> 4);
    const int krow_lane = (lane & 7) + ((lane >> 3) & 1) * 8;
    const int b_nadd = (lane >> 4) * 8;

#pragma unroll
    for (int kk = 0; kk < 8; kk++) {
        unsigned a0, a1, a2, a3;
        {
            int koff = kk * 16 + a_kchunk_base * 8;
            unsigned addr = (unsigned)__cvta_generic_to_shared(&sA[swz_off(arow, koff)]);
            asm volatile("ldmatrix.sync.aligned.m8n8.x4.shared.b16 {%0,%1,%2,%3}, [%4];"
                         : "=r"(a0), "=r"(a1), "=r"(a2), "=r"(a3) : "r"(addr));
        }
        const int krow = kk * 16 + krow_lane;
#pragma unroll
        for (int nb2 = 0; nb2 < 4; nb2++) {
            unsigned b0, b1, b2, b3;
            int ncol = nc * 64 + nb2 * 16 + b_nadd;
            unsigned addr = (unsigned)__cvta_generic_to_shared(&sB[swz_off(krow, ncol)]);
            asm volatile("ldmatrix.sync.aligned.m8n8.x4.trans.shared.b16 {%0,%1,%2,%3}, [%4];"
                         : "=r"(b0), "=r"(b1), "=r"(b2), "=r"(b3) : "r"(addr));
            float* c0 = acc[2 * nb2];
            asm volatile("mma.sync.aligned.m16n8k16.row.col.f32.f16.f16.f32 "
                         "{%0,%1,%2,%3}, {%4,%5,%6,%7}, {%8,%9}, {%0,%1,%2,%3};"
                         : "+f"(c0[0]), "+f"(c0[1]), "+f"(c0[2]), "+f"(c0[3])
                         : "r"(a0), "r"(a1), "r"(a2), "r"(a3), "r"(b0), "r"(b1));
            float* c1 = acc[2 * nb2 + 1];
            asm volatile("mma.sync.aligned.m16n8k16.row.col.f32.f16.f16.f32 "
                         "{%0,%1,%2,%3}, {%4,%5,%6,%7}, {%8,%9}, {%0,%1,%2,%3};"
                         : "+f"(c1[0]), "+f"(c1[1]), "+f"(c1[2]), "+f"(c1[3])
                         : "r"(a0), "r"(a1), "r"(a2), "r"(a3), "r"(b2), "r"(b3));
        }
    }

    const int row0 = mr * 16 + (lane >> 2);
    const int colb = (lane & 3) * 2;
#pragma unroll
    for (int nb = 0; nb < 8; nb++) {
        int col = nc * 64 + nb * 8 + colb;
        if (base + row0 < N) {
            __half2 h = __floats2half2_rn(acc[nb][0], acc[nb][1]);
            *(unsigned int*)&g_Gh[(size_t)(base + row0) * FD + col] = *(unsigned int*)&h;
        }
        if (base + row0 + 8 < N) {
            __half2 h = __floats2half2_rn(acc[nb][2], acc[nb][3]);
            *(unsigned int*)&g_Gh[(size_t)(base + row0 + 8) * FD + col] = *(unsigned int*)&h;
        }
    }
}

// ---------------------------------------------------------------------------
// Kernel 3: edge kernel on i-sorted packed edges. R6 load shape
// (4 edges/warp, LDG.64 rows), flat launch, with a warp-uniform fast path
// skipping duplicate G-row loads when all 4 slots share the same i.
// ---------------------------------------------------------------------------
__global__ __launch_bounds__(256) void edge_kernel(float* __restrict__ out, int E) {
    const int lane = threadIdx.x & 31;
    const int e0 = (blockIdx.x * 8 + (threadIdx.x >> 5)) * 4;
    if (e0 >= E) return;

    if (e0 + 4 <= E) {
        // Lanes 0..3 own edges e0..e0+3; other lanes mirror lane&3.
        int4 ed = __ldg(&g_edges[e0 + (lane & 3)]);
        const int i0 = __shfl_sync(0xffffffffu, ed.x, 0);
        const int i1 = __shfl_sync(0xffffffffu, ed.x, 1);
        const int i2 = __shfl_sync(0xffffffffu, ed.x, 2);
        const int i3 = __shfl_sync(0xffffffffu, ed.x, 3);
        const int j0 = __shfl_sync(0xffffffffu, ed.y, 0);
        const int j1 = __shfl_sync(0xffffffffu, ed.y, 1);
        const int j2 = __shfl_sync(0xffffffffu, ed.y, 2);
        const int j3 = __shfl_sync(0xffffffffu, ed.y, 3);

        uint2 fb0 = __ldg(&((const uint2*)(g_Fh + (size_t)j0 * FD))[lane]);
        uint2 fb1 = __ldg(&((const uint2*)(g_Fh + (size_t)j1 * FD))[lane]);
        uint2 fb2 = __ldg(&((const uint2*)(g_Fh + (size_t)j2 * FD))[lane]);
        uint2 fb3 = __ldg(&((const uint2*)(g_Fh + (size_t)j3 * FD))[lane]);

        uint2 ga0, ga1, ga2, ga3;
        if (i0 == i1 && i0 == i2 && i0 == i3) {
            // Sorted runs make this the common case (~90%).
            ga0 = __ldg(&((const uint2*)(g_Gh + (size_t)i0 * FD))[lane]);
            ga1 = ga0; ga2 = ga0; ga3 = ga0;
        } else {
            ga0 = __ldg(&((const uint2*)(g_Gh + (size_t)i0 * FD))[lane]);
            ga1 = __ldg(&((const uint2*)(g_Gh + (size_t)i1 * FD))[lane]);
            ga2 = __ldg(&((const uint2*)(g_Gh + (size_t)i2 * FD))[lane]);
            ga3 = __ldg(&((const uint2*)(g_Gh + (size_t)i3 * FD))[lane]);
        }

        float s0, s1, s2, s3;
        {
            float2 a0 = __half22float2(*(__half2*)&ga0.x), a1 = __half22float2(*(__half2*)&ga0.y);
            float2 b0 = __half22float2(*(__half2*)&fb0.x), b1 = __half22float2(*(__half2*)&fb0.y);
            s0 = a0.x * b0.x + a0.y * b0.y + a1.x * b1.x + a1.y * b1.y;
        }
        {
            float2 a0 = __half22float2(*(__half2*)&ga1.x), a1 = __half22float2(*(__half2*)&ga1.y);
            float2 b0 = __half22float2(*(__half2*)&fb1.x), b1 = __half22float2(*(__half2*)&fb1.y);
            s1 = a0.x * b0.x + a0.y * b0.y + a1.x * b1.x + a1.y * b1.y;
        }
        {
            float2 a0 = __half22float2(*(__half2*)&ga2.x), a1 = __half22float2(*(__half2*)&ga2.y);
            float2 b0 = __half22float2(*(__half2*)&fb2.x), b1 = __half22float2(*(__half2*)&fb2.y);
            s2 = a0.x * b0.x + a0.y * b0.y + a1.x * b1.x + a1.y * b1.y;
        }
        {
            float2 a0 = __half22float2(*(__half2*)&ga3.x), a1 = __half22float2(*(__half2*)&ga3.y);
            float2 b0 = __half22float2(*(__half2*)&fb3.x), b1 = __half22float2(*(__half2*)&fb3.y);
            s3 = a0.x * b0.x + a0.y * b0.y + a1.x * b1.x + a1.y * b1.y;
        }

#pragma unroll
        for (int o = 16; o; o >>= 1) {
            s0 += __shfl_xor_sync(0xffffffffu, s0, o);
            s1 += __shfl_xor_sync(0xffffffffu, s1, o);
            s2 += __shfl_xor_sync(0xffffffffu, s2, o);
            s3 += __shfl_xor_sync(0xffffffffu, s3, o);
        }

        if (lane < 4) {
            float sv = (lane == 0) ? s0 : (lane == 1) ? s1 : (lane == 2) ? s2 : s3;
            atomicAdd(out + ed.z, sv);   // ed.z = this lane's own edge's mol id
        }
    } else {
        // Tail (E not divisible by 4): per-edge full-warp.
        for (int e = e0; e < E; e++) {
            int4 ed = __ldg(&g_edges[e]);
            uint2 ga = __ldg(&((const uint2*)(g_Gh + (size_t)ed.x * FD))[lane]);
            uint2 fb = __ldg(&((const uint2*)(g_Fh + (size_t)ed.y * FD))[lane]);
            float2 a0 = __half22float2(*(__half2*)&ga.x), a1 = __half22float2(*(__half2*)&ga.y);
            float2 b0 = __half22float2(*(__half2*)&fb.x), b1 = __half22float2(*(__half2*)&fb.y);
            float s = a0.x * b0.x + a0.y * b0.y + a1.x * b1.x + a1.y * b1.y;
#pragma unroll
            for (int o = 16; o; o >>= 1) s += __shfl_xor_sync(0xffffffffu, s, o);
            if (lane == 0) atomicAdd(out + ed.z, s);
        }
    }
}

// ---------------------------------------------------------------------------
// Launch wrapper (graph-capturable: kernel launches only).
// Inputs: [0] feats f32 [N,128], [1] W f32 [128,128],
//         [2] nbr i32 [2,E], [3] mol i32 [E], [4] n_output (use out_size)
// Output: f32 [M]
// ---------------------------------------------------------------------------
extern "C" void kernel_launch(void* const* d_in, const int* in_sizes, int n_in,
                              void* d_out, int out_size) {
    const float* feats = (const float*)d_in[0];
    const float* W = (const float*)d_in[1];
    const int* nbr = (const int*)d_in[2];
    const int* mol = (const int*)d_in[3];
    float* out = (float*)d_out;

    const int N = in_sizes[0] / FD;
    const int E = in_sizes[2] / 2;
    const int M = out_size;

    int prep_elems = NMAX;
    if (M > prep_elems) prep_elems = M;
    prep_kernel<<<(prep_elems + 255) / 256, 256>>>(W, out, M);

    gemm_mma_kernel<<<(N + 63) / 64, 256>>>(feats, N);

    hist_kernel<<<(E + 255) / 256, 256>>>(nbr, E);
    scan_kernel<<<1, 1024>>>(N);
    scatter_kernel<<<(E + 255) / 256, 256>>>(nbr, mol, E);

    edge_kernel<<<(E + 31) / 32, 256>>>(out, E);
}

// round 12
// speedup vs baseline: 1.4969x; 1.4969x over previous
#include <cuda_runtime.h>
#include <cuda_fp16.h>

#define FD 128
#define NMAX 51200     // bins / node headroom over N=50000
#define EMAX 1700000   // edge headroom over E=1.6M
#define SCAN_BLK ((NMAX + 255) / 256)   // 200

// Scratch: Wh = (W + W^T) fp16, G = feats @ Ws (fp16), feats copy (fp16).
__device__ __half g_Wh[FD * FD];
__device__ __half g_Gh[(size_t)NMAX * FD];
__device__ __half g_Fh[(size_t)NMAX * FD];
// Sort scratch.
__device__ int  g_hist[NMAX];
__device__ int  g_cur[NMAX];
__device__ int  g_blk[SCAN_BLK];
__device__ int  g_blkoff[SCAN_BLK];
__device__ int4 g_edges[EMAX];

// ---------------------------------------------------------------------------
// Kernel 1: Wh = fp16(W + W^T); zero output; zero histogram.
// ---------------------------------------------------------------------------
__global__ void prep_kernel(const float* __restrict__ W,
                            float* __restrict__ out, int M) {
    int t = blockIdx.x * blockDim.x + threadIdx.x;
    if (t < FD * FD) {
        int r = t >> 7;
        int c = t & 127;
        g_Wh[t] = __float2half_rn(W[t] + W[c * FD + r]);
    }
    if (t < M) out[t] = 0.0f;
    if (t < NMAX) g_hist[t] = 0;
}

// ---------------------------------------------------------------------------
// Kernel 1b: histogram of source indices.
// ---------------------------------------------------------------------------
__global__ void hist_kernel(const int* __restrict__ nbr, int E) {
    int e = blockIdx.x * blockDim.x + threadIdx.x;
    if (e < E) atomicAdd(&g_hist[nbr[e]], 1);
}

// ---------------------------------------------------------------------------
// Multi-block exclusive scan over N bins (3 cheap kernels).
// ---------------------------------------------------------------------------
__global__ __launch_bounds__(256) void scanA_kernel(int N) {
    __shared__ int s[256];
    const int tid = threadIdx.x;
    const int bin = blockIdx.x * 256 + tid;
    int v = (bin < N) ? g_hist[bin] : 0;
    s[tid] = v;
    __syncthreads();
    for (int off = 1; off < 256; off <<= 1) {
        int t = (tid >= off) ? s[tid - off] : 0;
        __syncthreads();
        s[tid] += t;
        __syncthreads();
    }
    if (bin < N) g_cur[bin] = s[tid] - v;     // exclusive within block
    if (tid == 255) g_blk[blockIdx.x] = s[255];
}

__global__ __launch_bounds__(256) void scanB_kernel(int nblk) {
    __shared__ int s[256];
    const int tid = threadIdx.x;
    int v = (tid < nblk) ? g_blk[tid] : 0;
    s[tid] = v;
    __syncthreads();
    for (int off = 1; off < 256; off <<= 1) {
        int t = (tid >= off) ? s[tid - off] : 0;
        __syncthreads();
        s[tid] += t;
        __syncthreads();
    }
    if (tid < nblk) g_blkoff[tid] = s[tid] - v;   // exclusive block offsets
}

__global__ __launch_bounds__(256) void scanC_kernel(int N) {
    int bin = blockIdx.x * 256 + threadIdx.x;
    if (bin < N) g_cur[bin] += g_blkoff[blockIdx.x];
}

// ---------------------------------------------------------------------------
// Kernel 1d: scatter edges into i-sorted order (packed int4 per edge).
// ---------------------------------------------------------------------------
__global__ void scatter_kernel(const int* __restrict__ nbr,
                               const int* __restrict__ mol, int E) {
    int e = blockIdx.x * blockDim.x + threadIdx.x;
    if (e >= E) return;
    int i = nbr[e];
    int pos = atomicAdd(&g_cur[i], 1);
    g_edges[pos] = make_int4(i, nbr[(size_t)E + e], mol[e], 0);
}

// ---------------------------------------------------------------------------
// XOR swizzle on 16-byte chunks.
// ---------------------------------------------------------------------------
__device__ __forceinline__ int swz_off(int row, int col_halves) {
    int chunk = col_halves >> 3;
    int within = col_halves & 7;
    return row * FD + ((chunk ^ (row & 7)) << 3) + within;
}

// ---------------------------------------------------------------------------
// Kernel 2: G = feats @ Ws via HMMA (unchanged, measured-good since R6).
// ---------------------------------------------------------------------------
__global__ __launch_bounds__(256) void gemm_mma_kernel(const float* __restrict__ feats,
                                                       int N) {
    __shared__ __half sA[64 * FD];
    __shared__ __half sB[128 * FD];

    const int base = blockIdx.x * 64;
    const int tid = threadIdx.x;

    int nval = N - base;
    if (nval > 64) nval = 64;

    {
        const uint2* src = (const uint2*)g_Wh;
        for (int i = tid; i < 128 * 32; i += 256) {
            int row = i >> 5, c4 = i & 31;
            *(uint2*)&sB[swz_off(row, c4 * 4)] = src[i];
        }
    }
    {
        const float4* src = (const float4*)feats + (size_t)base * 32;
        uint2* fh_dst = (uint2*)(g_Fh + (size_t)base * FD);
        for (int i = tid; i < 64 * 32; i += 256) {
            int row = i >> 5, c4 = i & 31;
            uint2 p = make_uint2(0u, 0u);
            if (row < nval) {
                float4 v = src[i];
                __half2 h0 = __floats2half2_rn(v.x, v.y);
                __half2 h1 = __floats2half2_rn(v.z, v.w);
                p.x = *(unsigned int*)&h0;
                p.y = *(unsigned int*)&h1;
                fh_dst[i] = p;
            }
            *(uint2*)&sA[swz_off(row, c4 * 4)] = p;
        }
    }
    __syncthreads();

    const int warp = tid >> 5;
    const int lane = tid & 31;
    const int mr = warp >> 1;
    const int nc = warp & 1;

    float acc[8][4];
#pragma unroll
    for (int b = 0; b < 8; b++)
#pragma unroll
        for (int q = 0; q < 4; q++) acc[b][q] = 0.0f;

    const int arow = mr * 16 + (lane & 15);
    const int a_kchunk_base = (lane >> 4);
    const int krow_lane = (lane & 7) + ((lane >> 3) & 1) * 8;
    const int b_nadd = (lane >> 4) * 8;

#pragma unroll
    for (int kk = 0; kk < 8; kk++) {
        unsigned a0, a1, a2, a3;
        {
            int koff = kk * 16 + a_kchunk_base * 8;
            unsigned addr = (unsigned)__cvta_generic_to_shared(&sA[swz_off(arow, koff)]);
            asm volatile("ldmatrix.sync.aligned.m8n8.x4.shared.b16 {%0,%1,%2,%3}, [%4];"
                         : "=r"(a0), "=r"(a1), "=r"(a2), "=r"(a3) : "r"(addr));
        }
        const int krow = kk * 16 + krow_lane;
#pragma unroll
        for (int nb2 = 0; nb2 < 4; nb2++) {
            unsigned b0, b1, b2, b3;
            int ncol = nc * 64 + nb2 * 16 + b_nadd;
            unsigned addr = (unsigned)__cvta_generic_to_shared(&sB[swz_off(krow, ncol)]);
            asm volatile("ldmatrix.sync.aligned.m8n8.x4.trans.shared.b16 {%0,%1,%2,%3}, [%4];"
                         : "=r"(b0), "=r"(b1), "=r"(b2), "=r"(b3) : "r"(addr));
            float* c0 = acc[2 * nb2];
            asm volatile("mma.sync.aligned.m16n8k16.row.col.f32.f16.f16.f32 "
                         "{%0,%1,%2,%3}, {%4,%5,%6,%7}, {%8,%9}, {%0,%1,%2,%3};"
                         : "+f"(c0[0]), "+f"(c0[1]), "+f"(c0[2]), "+f"(c0[3])
                         : "r"(a0), "r"(a1), "r"(a2), "r"(a3), "r"(b0), "r"(b1));
            float* c1 = acc[2 * nb2 + 1];
            asm volatile("mma.sync.aligned.m16n8k16.row.col.f32.f16.f16.f32 "
                         "{%0,%1,%2,%3}, {%4,%5,%6,%7}, {%8,%9}, {%0,%1,%2,%3};"
                         : "+f"(c1[0]), "+f"(c1[1]), "+f"(c1[2]), "+f"(c1[3])
                         : "r"(a0), "r"(a1), "r"(a2), "r"(a3), "r"(b2), "r"(b3));
        }
    }

    const int row0 = mr * 16 + (lane >> 2);
    const int colb = (lane & 3) * 2;
#pragma unroll
    for (int nb = 0; nb < 8; nb++) {
        int col = nc * 64 + nb * 8 + colb;
        if (base + row0 < N) {
            __half2 h = __floats2half2_rn(acc[nb][0], acc[nb][1]);
            *(unsigned int*)&g_Gh[(size_t)(base + row0) * FD + col] = *(unsigned int*)&h;
        }
        if (base + row0 + 8 < N) {
            __half2 h = __floats2half2_rn(acc[nb][2], acc[nb][3]);
            *(unsigned int*)&g_Gh[(size_t)(base + row0 + 8) * FD + col] = *(unsigned int*)&h;
        }
    }
}

// ---------------------------------------------------------------------------
// Kernel 3: edge kernel on i-sorted packed edges (unchanged from R11).
// ---------------------------------------------------------------------------
__global__ __launch_bounds__(256) void edge_kernel(float* __restrict__ out, int E) {
    const int lane = threadIdx.x & 31;
    const int e0 = (blockIdx.x * 8 + (threadIdx.x >> 5)) * 4;
    if (e0 >= E) return;

    if (e0 + 4 <= E) {
        int4 ed = __ldg(&g_edges[e0 + (lane & 3)]);
        const int i0 = __shfl_sync(0xffffffffu, ed.x, 0);
        const int i1 = __shfl_sync(0xffffffffu, ed.x, 1);
        const int i2 = __shfl_sync(0xffffffffu, ed.x, 2);
        const int i3 = __shfl_sync(0xffffffffu, ed.x, 3);
        const int j0 = __shfl_sync(0xffffffffu, ed.y, 0);
        const int j1 = __shfl_sync(0xffffffffu, ed.y, 1);
        const int j2 = __shfl_sync(0xffffffffu, ed.y, 2);
        const int j3 = __shfl_sync(0xffffffffu, ed.y, 3);

        uint2 fb0 = __ldg(&((const uint2*)(g_Fh + (size_t)j0 * FD))[lane]);
        uint2 fb1 = __ldg(&((const uint2*)(g_Fh + (size_t)j1 * FD))[lane]);
        uint2 fb2 = __ldg(&((const uint2*)(g_Fh + (size_t)j2 * FD))[lane]);
        uint2 fb3 = __ldg(&((const uint2*)(g_Fh + (size_t)j3 * FD))[lane]);

        uint2 ga0, ga1, ga2, ga3;
        if (i0 == i1 && i0 == i2 && i0 == i3) {
            ga0 = __ldg(&((const uint2*)(g_Gh + (size_t)i0 * FD))[lane]);
            ga1 = ga0; ga2 = ga0; ga3 = ga0;
        } else {
            ga0 = __ldg(&((const uint2*)(g_Gh + (size_t)i0 * FD))[lane]);
            ga1 = __ldg(&((const uint2*)(g_Gh + (size_t)i1 * FD))[lane]);
            ga2 = __ldg(&((const uint2*)(g_Gh + (size_t)i2 * FD))[lane]);
            ga3 = __ldg(&((const uint2*)(g_Gh + (size_t)i3 * FD))[lane]);
        }

        float s0, s1, s2, s3;
        {
            float2 a0 = __half22float2(*(__half2*)&ga0.x), a1 = __half22float2(*(__half2*)&ga0.y);
            float2 b0 = __half22float2(*(__half2*)&fb0.x), b1 = __half22float2(*(__half2*)&fb0.y);
            s0 = a0.x * b0.x + a0.y * b0.y + a1.x * b1.x + a1.y * b1.y;
        }
        {
            float2 a0 = __half22float2(*(__half2*)&ga1.x), a1 = __half22float2(*(__half2*)&ga1.y);
            float2 b0 = __half22float2(*(__half2*)&fb1.x), b1 = __half22float2(*(__half2*)&fb1.y);
            s1 = a0.x * b0.x + a0.y * b0.y + a1.x * b1.x + a1.y * b1.y;
        }
        {
            float2 a0 = __half22float2(*(__half2*)&ga2.x), a1 = __half22float2(*(__half2*)&ga2.y);
            float2 b0 = __half22float2(*(__half2*)&fb2.x), b1 = __half22float2(*(__half2*)&fb2.y);
            s2 = a0.x * b0.x + a0.y * b0.y + a1.x * b1.x + a1.y * b1.y;
        }
        {
            float2 a0 = __half22float2(*(__half2*)&ga3.x), a1 = __half22float2(*(__half2*)&ga3.y);
            float2 b0 = __half22float2(*(__half2*)&fb3.x), b1 = __half22float2(*(__half2*)&fb3.y);
            s3 = a0.x * b0.x + a0.y * b0.y + a1.x * b1.x + a1.y * b1.y;
        }

#pragma unroll
        for (int o = 16; o; o >>= 1) {
            s0 += __shfl_xor_sync(0xffffffffu, s0, o);
            s1 += __shfl_xor_sync(0xffffffffu, s1, o);
            s2 += __shfl_xor_sync(0xffffffffu, s2, o);
            s3 += __shfl_xor_sync(0xffffffffu, s3, o);
        }

        if (lane < 4) {
            float sv = (lane == 0) ? s0 : (lane == 1) ? s1 : (lane == 2) ? s2 : s3;
            atomicAdd(out + ed.z, sv);
        }
    } else {
        for (int e = e0; e < E; e++) {
            int4 ed = __ldg(&g_edges[e]);
            uint2 ga = __ldg(&((const uint2*)(g_Gh + (size_t)ed.x * FD))[lane]);
            uint2 fb = __ldg(&((const uint2*)(g_Fh + (size_t)ed.y * FD))[lane]);
            float2 a0 = __half22float2(*(__half2*)&ga.x), a1 = __half22float2(*(__half2*)&ga.y);
            float2 b0 = __half22float2(*(__half2*)&fb.x), b1 = __half22float2(*(__half2*)&fb.y);
            float s = a0.x * b0.x + a0.y * b0.y + a1.x * b1.x + a1.y * b1.y;
#pragma unroll
            for (int o = 16; o; o >>= 1) s += __shfl_xor_sync(0xffffffffu, s, o);
            if (lane == 0) atomicAdd(out + ed.z, s);
        }
    }
}

// ---------------------------------------------------------------------------
// Launch wrapper (graph-capturable: kernel launches only).
// Inputs: [0] feats f32 [N,128], [1] W f32 [128,128],
//         [2] nbr i32 [2,E], [3] mol i32 [E], [4] n_output (use out_size)
// Output: f32 [M]
// ---------------------------------------------------------------------------
extern "C" void kernel_launch(void* const* d_in, const int* in_sizes, int n_in,
                              void* d_out, int out_size) {
    const float* feats = (const float*)d_in[0];
    const float* W = (const float*)d_in[1];
    const int* nbr = (const int*)d_in[2];
    const int* mol = (const int*)d_in[3];
    float* out = (float*)d_out;

    const int N = in_sizes[0] / FD;
    const int E = in_sizes[2] / 2;
    const int M = out_size;

    int prep_elems = NMAX;
    if (M > prep_elems) prep_elems = M;
    prep_kernel<<<(prep_elems + 255) / 256, 256>>>(W, out, M);

    gemm_mma_kernel<<<(N + 63) / 64, 256>>>(feats, N);

    hist_kernel<<<(E + 255) / 256, 256>>>(nbr, E);

    const int nblk = (N + 255) / 256;      // <= SCAN_BLK, <= 256
    scanA_kernel<<<nblk, 256>>>(N);
    scanB_kernel<<<1, 256>>>(nblk);
    scanC_kernel<<<nblk, 256>>>(N);

    scatter_kernel<<<(E + 255) / 256, 256>>>(nbr, mol, E);

    edge_kernel<<<(E + 31) / 32, 256>>>(out, E);
}

// round 15
// speedup vs baseline: 1.8581x; 1.2413x over previous
#include <cuda_runtime.h>
#include <cuda_fp16.h>

#define FD 128
#define NMAX 51200   // headroom over N=50000

// Scratch: Wh = (W + W^T) fp16, G = feats @ Ws (fp16), feats copy (fp16).
__device__ __half g_Wh[FD * FD];
__device__ __half g_Gh[(size_t)NMAX * FD];
__device__ __half g_Fh[(size_t)NMAX * FD];

// ---------------------------------------------------------------------------
// Kernel 1: Wh = fp16(W + W^T).
// ---------------------------------------------------------------------------
__global__ void prep_kernel(const float* __restrict__ W) {
    int t = blockIdx.x * blockDim.x + threadIdx.x;
    if (t < FD * FD) {
        int r = t >> 7;
        int c = t & 127;
        g_Wh[t] = __float2half_rn(W[t] + W[c * FD + r]);
    }
}

// ---------------------------------------------------------------------------
// Kernel 3 (launch position #3): zero the poisoned output.
// Split from prep so edge_kernel is the 4th launch -> ncu profiles it.
// ---------------------------------------------------------------------------
__global__ void zero_kernel(float* __restrict__ out, int M) {
    int t = blockIdx.x * blockDim.x + threadIdx.x;
    if (t < M) out[t] = 0.0f;
}

// ---------------------------------------------------------------------------
// XOR swizzle on 16-byte chunks.
// ---------------------------------------------------------------------------
__device__ __forceinline__ int swz_off(int row, int col_halves) {
    int chunk = col_halves >> 3;
    int within = col_halves & 7;
    return row * FD + ((chunk ^ (row & 7)) << 3) + within;
}

// ---------------------------------------------------------------------------
// Kernel 2: G = feats @ Ws via HMMA (unchanged, measured-good since R6).
// ---------------------------------------------------------------------------
__global__ __launch_bounds__(256) void gemm_mma_kernel(const float* __restrict__ feats,
                                                       int N) {
    __shared__ __half sA[64 * FD];
    __shared__ __half sB[128 * FD];

    const int base = blockIdx.x * 64;
    const int tid = threadIdx.x;

    int nval = N - base;
    if (nval > 64) nval = 64;

    {
        const uint2* src = (const uint2*)g_Wh;
        for (int i = tid; i < 128 * 32; i += 256) {
            int row = i >> 5, c4 = i & 31;
            *(uint2*)&sB[swz_off(row, c4 * 4)] = src[i];
        }
    }
    {
        const float4* src = (const float4*)feats + (size_t)base * 32;
        uint2* fh_dst = (uint2*)(g_Fh + (size_t)base * FD);
        for (int i = tid; i < 64 * 32; i += 256) {
            int row = i >> 5, c4 = i & 31;
            uint2 p = make_uint2(0u, 0u);
            if (row < nval) {
                float4 v = src[i];
                __half2 h0 = __floats2half2_rn(v.x, v.y);
                __half2 h1 = __floats2half2_rn(v.z, v.w);
                p.x = *(unsigned int*)&h0;
                p.y = *(unsigned int*)&h1;
                fh_dst[i] = p;
            }
            *(uint2*)&sA[swz_off(row, c4 * 4)] = p;
        }
    }
    __syncthreads();

    const int warp = tid >> 5;
    const int lane = tid & 31;
    const int mr = warp >> 1;
    const int nc = warp & 1;

    float acc[8][4];
#pragma unroll
    for (int b = 0; b < 8; b++)
#pragma unroll
        for (int q = 0; q < 4; q++) acc[b][q] = 0.0f;

    const int arow = mr * 16 + (lane & 15);
    const int a_kchunk_base = (lane >> 4);
    const int krow_lane = (lane & 7) + ((lane >> 3) & 1) * 8;
    const int b_nadd = (lane >> 4) * 8;

#pragma unroll
    for (int kk = 0; kk < 8; kk++) {
        unsigned a0, a1, a2, a3;
        {
            int koff = kk * 16 + a_kchunk_base * 8;
            unsigned addr = (unsigned)__cvta_generic_to_shared(&sA[swz_off(arow, koff)]);
            asm volatile("ldmatrix.sync.aligned.m8n8.x4.shared.b16 {%0,%1,%2,%3}, [%4];"
                         : "=r"(a0), "=r"(a1), "=r"(a2), "=r"(a3) : "r"(addr));
        }
        const int krow = kk * 16 + krow_lane;
#pragma unroll
        for (int nb2 = 0; nb2 < 4; nb2++) {
            unsigned b0, b1, b2, b3;
            int ncol = nc * 64 + nb2 * 16 + b_nadd;
            unsigned addr = (unsigned)__cvta_generic_to_shared(&sB[swz_off(krow, ncol)]);
            asm volatile("ldmatrix.sync.aligned.m8n8.x4.trans.shared.b16 {%0,%1,%2,%3}, [%4];"
                         : "=r"(b0), "=r"(b1), "=r"(b2), "=r"(b3) : "r"(addr));
            float* c0 = acc[2 * nb2];
            asm volatile("mma.sync.aligned.m16n8k16.row.col.f32.f16.f16.f32 "
                         "{%0,%1,%2,%3}, {%4,%5,%6,%7}, {%8,%9}, {%0,%1,%2,%3};"
                         : "+f"(c0[0]), "+f"(c0[1]), "+f"(c0[2]), "+f"(c0[3])
                         : "r"(a0), "r"(a1), "r"(a2), "r"(a3), "r"(b0), "r"(b1));
            float* c1 = acc[2 * nb2 + 1];
            asm volatile("mma.sync.aligned.m16n8k16.row.col.f32.f16.f16.f32 "
                         "{%0,%1,%2,%3}, {%4,%5,%6,%7}, {%8,%9}, {%0,%1,%2,%3};"
                         : "+f"(c1[0]), "+f"(c1[1]), "+f"(c1[2]), "+f"(c1[3])
                         : "r"(a0), "r"(a1), "r"(a2), "r"(a3), "r"(b2), "r"(b3));
        }
    }

    const int row0 = mr * 16 + (lane >> 2);
    const int colb = (lane & 3) * 2;
#pragma unroll
    for (int nb = 0; nb < 8; nb++) {
        int col = nc * 64 + nb * 8 + colb;
        if (base + row0 < N) {
            __half2 h = __floats2half2_rn(acc[nb][0], acc[nb][1]);
            *(unsigned int*)&g_Gh[(size_t)(base + row0) * FD + col] = *(unsigned int*)&h;
        }
        if (base + row0 + 8 < N) {
            __half2 h = __floats2half2_rn(acc[nb][2], acc[nb][3]);
            *(unsigned int*)&g_Gh[(size_t)(base + row0 + 8) * FD + col] = *(unsigned int*)&h;
        }
    }
}

// ---------------------------------------------------------------------------
// Kernel 4: edge kernel — exact R6 shape (best measured): flat launch,
// 4 edges/warp, 8x LDG.64 full-warp rows, butterfly reduce, 4 REDGs.
// ---------------------------------------------------------------------------
__global__ __launch_bounds__(256) void edge_kernel(const int* __restrict__ nbr,
                                                   const int* __restrict__ mol,
                                                   float* __restrict__ out, int E) {
    const int e0 = (blockIdx.x * 8 + (threadIdx.x >> 5)) * 4;
    if (e0 >= E) return;
    const int lane = threadIdx.x & 31;

    if (e0 + 4 <= E) {
        int4 ii = __ldg((const int4*)(nbr + e0));
        int4 jj = __ldg((const int4*)(nbr + (size_t)E + e0));

        uint2 ga0 = __ldg(&((const uint2*)(g_Gh + (size_t)ii.x * FD))[lane]);
        uint2 ga1 = __ldg(&((const uint2*)(g_Gh + (size_t)ii.y * FD))[lane]);
        uint2 ga2 = __ldg(&((const uint2*)(g_Gh + (size_t)ii.z * FD))[lane]);
        uint2 ga3 = __ldg(&((const uint2*)(g_Gh + (size_t)ii.w * FD))[lane]);
        uint2 fb0 = __ldg(&((const uint2*)(g_Fh + (size_t)jj.x * FD))[lane]);
        uint2 fb1 = __ldg(&((const uint2*)(g_Fh + (size_t)jj.y * FD))[lane]);
        uint2 fb2 = __ldg(&((const uint2*)(g_Fh + (size_t)jj.z * FD))[lane]);
        uint2 fb3 = __ldg(&((const uint2*)(g_Fh + (size_t)jj.w * FD))[lane]);

        float s0, s1, s2, s3;
        {
            float2 a0 = __half22float2(*(__half2*)&ga0.x), a1 = __half22float2(*(__half2*)&ga0.y);
            float2 b0 = __half22float2(*(__half2*)&fb0.x), b1 = __half22float2(*(__half2*)&fb0.y);
            s0 = a0.x * b0.x + a0.y * b0.y + a1.x * b1.x + a1.y * b1.y;
        }
        {
            float2 a0 = __half22float2(*(__half2*)&ga1.x), a1 = __half22float2(*(__half2*)&ga1.y);
            float2 b0 = __half22float2(*(__half2*)&fb1.x), b1 = __half22float2(*(__half2*)&fb1.y);
            s1 = a0.x * b0.x + a0.y * b0.y + a1.x * b1.x + a1.y * b1.y;
        }
        {
            float2 a0 = __half22float2(*(__half2*)&ga2.x), a1 = __half22float2(*(__half2*)&ga2.y);
            float2 b0 = __half22float2(*(__half2*)&fb2.x), b1 = __half22float2(*(__half2*)&fb2.y);
            s2 = a0.x * b0.x + a0.y * b0.y + a1.x * b1.x + a1.y * b1.y;
        }
        {
            float2 a0 = __half22float2(*(__half2*)&ga3.x), a1 = __half22float2(*(__half2*)&ga3.y);
            float2 b0 = __half22float2(*(__half2*)&fb3.x), b1 = __half22float2(*(__half2*)&fb3.y);
            s3 = a0.x * b0.x + a0.y * b0.y + a1.x * b1.x + a1.y * b1.y;
        }

#pragma unroll
        for (int o = 16; o; o >>= 1) {
            s0 += __shfl_xor_sync(0xffffffffu, s0, o);
            s1 += __shfl_xor_sync(0xffffffffu, s1, o);
            s2 += __shfl_xor_sync(0xffffffffu, s2, o);
            s3 += __shfl_xor_sync(0xffffffffu, s3, o);
        }

        if (lane < 4) {
            int4 mm = __ldg((const int4*)(mol + e0));
            float sv = (lane == 0) ? s0 : (lane == 1) ? s1 : (lane == 2) ? s2 : s3;
            int mv = (lane == 0) ? mm.x : (lane == 1) ? mm.y : (lane == 2) ? mm.z : mm.w;
            atomicAdd(out + mv, sv);
        }
    } else {
        // Tail (E not divisible by 4): per-edge full-warp.
        for (int e = e0; e < E; e++) {
            int i = __ldg(&nbr[e]);
            int j = __ldg(&nbr[(size_t)E + e]);
            uint2 ga = __ldg(&((const uint2*)(g_Gh + (size_t)i * FD))[lane]);
            uint2 fb = __ldg(&((const uint2*)(g_Fh + (size_t)j * FD))[lane]);
            float2 a0 = __half22float2(*(__half2*)&ga.x), a1 = __half22float2(*(__half2*)&ga.y);
            float2 b0 = __half22float2(*(__half2*)&fb.x), b1 = __half22float2(*(__half2*)&fb.y);
            float s = a0.x * b0.x + a0.y * b0.y + a1.x * b1.x + a1.y * b1.y;
#pragma unroll
            for (int o = 16; o; o >>= 1) s += __shfl_xor_sync(0xffffffffu, s, o);
            if (lane == 0) atomicAdd(out + __ldg(&mol[e]), s);
        }
    }
}

// ---------------------------------------------------------------------------
// Launch wrapper (graph-capturable: kernel launches only).
// Launch order chosen so edge_kernel is the 4th launch (ncu capture slot).
// Inputs: [0] feats f32 [N,128], [1] W f32 [128,128],
//         [2] nbr i32 [2,E], [3] mol i32 [E], [4] n_output (use out_size)
// Output: f32 [M]
// ---------------------------------------------------------------------------
extern "C" void kernel_launch(void* const* d_in, const int* in_sizes, int n_in,
                              void* d_out, int out_size) {
    const float* feats = (const float*)d_in[0];
    const float* W = (const float*)d_in[1];
    const int* nbr = (const int*)d_in[2];
    const int* mol = (const int*)d_in[3];
    float* out = (float*)d_out;

    const int N = in_sizes[0] / FD;
    const int E = in_sizes[2] / 2;
    const int M = out_size;

    prep_kernel<<<(FD * FD + 255) / 256, 256>>>(W);           // launch 1
    gemm_mma_kernel<<<(N + 63) / 64, 256>>>(feats, N);        // launch 2
    zero_kernel<<<(M + 255) / 256, 256>>>(out, M);            // launch 3
    edge_kernel<<<(E + 31) / 32, 256>>>(nbr, mol, out, E);    // launch 4 (profiled)
}